// round 1
// baseline (speedup 1.0000x reference)
#include <cuda_runtime.h>
#include <math.h>

#define Sq 2048
#define DK 64
#define TQ 16
#define KT 64
#define NTHR 256
#define NBH 64  // B*H

// SMEM floats layout:
//   scores [TQ][Sq]            = 32768
//   q_s    [DK][TQ]            = 1024
//   kv_s   [64][65]            = 4160
//   pf     [TQ][64]            = 1024
//   pc     [TQ][64]            = 1024
//   inv    [TQ]                = 16
#define SMEM_FLOATS (TQ*Sq + DK*TQ + 64*65 + TQ*64*2 + TQ)

__global__ __launch_bounds__(NTHR, 1)
void sdpa_kernel(const float* __restrict__ Q,
                 const float* __restrict__ K,
                 const float* __restrict__ V,
                 float* __restrict__ out_ctx,
                 float* __restrict__ out_attn)
{
    extern __shared__ float sm[];
    float* scores = sm;                     // [TQ][Sq]  exp(s), later normalized attn
    float* q_s    = scores + TQ * Sq;       // [DK][TQ]  (d-major)
    float* kv_s   = q_s + DK * TQ;          // [64][65]  K: [d][k] pad65 ; V: [k][d] pad65
    float* pf     = kv_s + 64 * 65;         // [TQ][64]
    float* pc     = pf + TQ * 64;           // [TQ][64]
    float* inv    = pc + TQ * 64;           // [TQ]

    const int t  = threadIdx.x;
    const int bh = blockIdx.y;
    const int q0 = blockIdx.x * TQ;
    const float scale = 0.125f;             // 1/sqrt(64)

    const float* Qb = Q + (size_t)bh * Sq * DK;
    const float* Kb = K + (size_t)bh * Sq * DK;
    const float* Vb = V + (size_t)bh * Sq * DK;

    // ---- load Q tile transposed: q_s[d][q] ----
    {
        int d = t & 63;
        for (int q = t >> 6; q < TQ; q += 4)
            q_s[d * TQ + q] = Qb[(size_t)(q0 + q) * DK + d];
    }

    const int lane_k = t & 63;   // key (phase 1) / dv (phase 3) lane
    const int qg     = t >> 6;   // 0..3, handles queries qg*4 .. qg*4+3
    float sfull[4] = {0.f,0.f,0.f,0.f};
    float scaus[4] = {0.f,0.f,0.f,0.f};

    // ======== Phase 1: scores = exp(QK^T * scale), row sums ========
    for (int kt = 0; kt < Sq / KT; kt++) {
        __syncthreads();
        // load K tile transposed: kv_s[d][k], stride 65 (conflict-free ld/st)
        #pragma unroll
        for (int i = 0; i < 16; i++) {
            int l = t + i * NTHR;
            int k = l >> 6, d = l & 63;
            kv_s[d * 65 + k] = Kb[(size_t)(kt * KT + k) * DK + d];
        }
        __syncthreads();

        float acc0 = 0.f, acc1 = 0.f, acc2 = 0.f, acc3 = 0.f;
        #pragma unroll
        for (int d = 0; d < DK; d++) {
            float kv = kv_s[d * 65 + lane_k];
            const float4 q4 = *(const float4*)&q_s[d * TQ + qg * 4];
            acc0 += q4.x * kv; acc1 += q4.y * kv;
            acc2 += q4.z * kv; acc3 += q4.w * kv;
        }
        float accv[4] = {acc0, acc1, acc2, acc3};
        int kg = kt * KT + lane_k;
        #pragma unroll
        for (int i = 0; i < 4; i++) {
            float e = __expf(accv[i] * scale);
            int qglob = q0 + qg * 4 + i;
            sfull[i] += e;
            if (kg <= qglob) scaus[i] += e;
            scores[(qg * 4 + i) * Sq + kg] = e;
        }
    }

    // ======== Phase 1.5: reduce denominators ========
    #pragma unroll
    for (int i = 0; i < 4; i++) {
        pf[(qg * 4 + i) * 64 + lane_k] = sfull[i];
        pc[(qg * 4 + i) * 64 + lane_k] = scaus[i];
    }
    __syncthreads();
    if (t < TQ) {
        float sf = 0.f, sc = 0.f;
        #pragma unroll 8
        for (int j = 0; j < 64; j++) { sf += pf[t * 64 + j]; sc += pc[t * 64 + j]; }
        inv[t] = 1.0f / (sc + 1e-8f * sf);
    }
    __syncthreads();

    // ======== Phase 2: normalize + causal mask; write attn; store back ========
    {
        float* attn_base = out_attn + ((size_t)bh * Sq + q0) * Sq;
        #pragma unroll 4
        for (int idx = t; idx < TQ * Sq; idx += NTHR) {
            int q = idx >> 11;            // /Sq
            int k = idx & (Sq - 1);
            float a = (k <= q0 + q) ? scores[idx] * inv[q] : 0.0f;
            scores[idx] = a;
            attn_base[(size_t)q * Sq + k] = a;
        }
    }

    // ======== Phase 3: context = attn @ V (causal tiles only) ========
    const int dv = lane_k;
    float ctx0 = 0.f, ctx1 = 0.f, ctx2 = 0.f, ctx3 = 0.f;
    const int ntiles = (q0 + TQ - 1) / KT + 1;
    for (int kt = 0; kt < ntiles; kt++) {
        __syncthreads();
        // load V tile natural: kv_s[k][d], stride 65
        #pragma unroll
        for (int i = 0; i < 16; i++) {
            int l = t + i * NTHR;
            int k = l >> 6, d = l & 63;
            kv_s[k * 65 + d] = Vb[(size_t)(kt * KT + k) * DK + d];
        }
        __syncthreads();
        const float* srow = scores + qg * 4 * Sq + kt * KT;
        #pragma unroll 4
        for (int kk = 0; kk < KT; kk++) {
            float v = kv_s[kk * 65 + dv];
            ctx0 += srow[kk]          * v;
            ctx1 += srow[Sq + kk]     * v;
            ctx2 += srow[2 * Sq + kk] * v;
            ctx3 += srow[3 * Sq + kk] * v;
        }
    }
    float* ctx_base = out_ctx + ((size_t)bh * Sq + q0 + qg * 4) * DK + dv;
    ctx_base[0]      = ctx0;
    ctx_base[DK]     = ctx1;
    ctx_base[2 * DK] = ctx2;
    ctx_base[3 * DK] = ctx3;
}

extern "C" void kernel_launch(void* const* d_in, const int* in_sizes, int n_in,
                              void* d_out, int out_size)
{
    const float* Q = (const float*)d_in[0];
    const float* K = (const float*)d_in[1];
    const float* V = (const float*)d_in[2];
    // output tuple: (context [B,H,S,DK], attn [B,H,S,S]) concatenated
    float* ctx  = (float*)d_out;
    float* attn = (float*)d_out + (size_t)NBH * Sq * DK;

    static int smem_set = 0;
    int smem_bytes = SMEM_FLOATS * (int)sizeof(float);
    cudaFuncSetAttribute(sdpa_kernel, cudaFuncAttributeMaxDynamicSharedMemorySize, smem_bytes);

    dim3 grid(Sq / TQ, NBH);
    sdpa_kernel<<<grid, NTHR, smem_bytes>>>(Q, K, V, ctx, attn);
    (void)in_sizes; (void)n_in; (void)out_size; (void)smem_set;
}